// round 1
// baseline (speedup 1.0000x reference)
#include <cuda_runtime.h>
#include <cuda_bf16.h>
#include <math.h>

// ---------------------------------------------------------------------------
// Soft-VM single step. Key observation: eq_gate/silu_threshold with SCALE=20
// decay like exp(-20*|diff|) -> exactly 0 in fp32 beyond |diff| ~ 5. So soft
// reads/writes over the 16M-entry memory are supported on +/-8 windows around
// the (integer-valued) addresses. The only bulk work is copying memory to the
// output (128 MB of HBM traffic -> the roofline).
// ---------------------------------------------------------------------------

#define SCALE_F 20.0f

__device__ __forceinline__ float silu_f(float x) {
    // x * sigmoid(x); expf(-x) overflows to +inf for very negative x -> silu=0,
    // matching jax within fp32 tolerance (subnormal tails irrelevant here).
    return x / (1.0f + expf(-x));
}

__device__ __forceinline__ float silu_th(float x) {
    float d = SCALE_F * x;
    return (silu_f(d + 0.5f * SCALE_F) - silu_f(d - 0.5f * SCALE_F)) / SCALE_F;
}

__device__ __forceinline__ float sw_mul(float a, float b) {
    return a * silu_f(b) - a * silu_f(-b);
}

__device__ __forceinline__ float eq_g(float a, float b) {
    float diff = a - b;
    return silu_th(diff + 0.5f) * silu_th(-diff + 0.5f);
}

__device__ __forceinline__ float ge_g(float a, float b) {
    return silu_th(a - b + 0.5f);
}

__device__ __forceinline__ float gt_g(float a, float b) {
    return silu_th(a - b - 0.5f);
}

__device__ __forceinline__ float pulse_f(float x, float c) {
    float d = x - c;
    return sw_mul(silu_th(d + 0.5f), silu_th(-d + 0.5f));
}

// Windowed soft-attention read: weights outside +/-8 underflow to 0 in fp32.
__device__ float read_mem_win(const float* __restrict__ mem, float addr, int memn) {
    float cl = fminf(fmaxf(addr, -64.0f), (float)memn + 64.0f);
    long long c = llrintf(cl);
    float wsum = 0.0f, acc = 0.0f;
    #pragma unroll
    for (int k = -8; k <= 8; k++) {
        long long p = c + k;
        if (p < 0 || p >= (long long)memn) continue;
        float w = eq_g(addr, (float)p);
        wsum += w;
        acc  += w * mem[p];
    }
    return acc / (wsum + 1e-8f);
}

// Opcodes
#define OP_LEA 0
#define OP_IMM 1
#define OP_JMP 2
#define OP_JSR 3
#define OP_BZ  4
#define OP_BNZ 5
#define OP_ENT 6
#define OP_ADJ 7
#define OP_LEV 8
#define OP_LI  9
#define OP_LC  10
#define OP_SI  11
#define OP_SC  12
#define OP_PSH 13
#define OP_OR  14
#define OP_XOR 15
#define OP_AND 16
#define OP_EQ  17
#define OP_NE  18
#define OP_LT  19
#define OP_GT  20
#define OP_LE  21
#define OP_GE  22
#define OP_SHL 23
#define OP_SHR 24
#define OP_ADD 25
#define OP_SUB 26
#define OP_MUL 27
#define OP_DIV 28
#define OP_MOD 29

// ---------------------------------------------------------------------------
// Kernel 1: bulk copy memory -> out[4..]
// ---------------------------------------------------------------------------
__global__ void copy_mem_kernel(const float4* __restrict__ src,
                                float4* __restrict__ dst, int n4) {
    int i = blockIdx.x * blockDim.x + threadIdx.x;
    if (i < n4) dst[i] = src[i];
}

// ---------------------------------------------------------------------------
// Kernel 2: one block, 256 threads. Computes the full step and patches the
// write windows in out.
// ---------------------------------------------------------------------------
__global__ void step_kernel(const float* __restrict__ mem,
                            const float* __restrict__ pcp,
                            const float* __restrict__ spp,
                            const float* __restrict__ bpp,
                            const float* __restrict__ axp,
                            float* __restrict__ out, int memn) {
    __shared__ float s_div[256];
    __shared__ float s_shl[32];
    __shared__ float s_shr[32];
    __shared__ float s_reads[5];   // [inst, stack_top, mem[ax], bp_from_stack, pc_from_stack]
    __shared__ float s_wa[5];      // write addresses (float, gated)
    __shared__ float s_wv[5];      // write values

    int tid = threadIdx.x;
    float pc = *pcp, sp = *spp, bp = *bpp, ax = *axp;

    // Phase 1: the 5 soft reads (all on ORIGINAL memory, per reference)
    if (tid < 5) {
        float addr = (tid == 0) ? pc
                   : (tid == 1) ? sp
                   : (tid == 2) ? ax
                   : (tid == 3) ? bp
                   : (sp + 8.0f);
        s_reads[tid] = read_mem_win(mem, addr, memn);
    }
    __syncthreads();

    float stack_top = s_reads[1];
    float ax_safe = ax + eq_g(ax, 0.0f);

    // Phase 2a: swiglu_div terms, one q per thread
    {
        float q = (float)tid;
        float a = stack_top, b = ax_safe;
        float t1 = a - q * b + 0.5f;
        float th1 = (silu_f(SCALE_F * (t1 + 0.5f)) - silu_f(SCALE_F * (t1 - 0.5f))) / SCALE_F;
        float t2 = a - (q + 1.0f) * b + 0.5f;
        float th2 = (silu_f(SCALE_F * (t2 + 0.5f)) - silu_f(SCALE_F * (t2 - 0.5f))) / SCALE_F;
        s_div[tid] = (th1 - th2) * q;
    }
    // Phase 2b: shift terms, one i per thread (threads 0..31)
    if (tid < 32) {
        float fi = (float)tid;
        float p2 = exp2f(fi);
        float pul = pulse_f(ax, fi);
        s_shl[tid] = sw_mul(stack_top, p2) * pul;
        s_shr[tid] = floorf(stack_top / p2) * pul;
    }
    __syncthreads();

    // Phase 3: thread 0 combines everything (serial, ~few hundred flops)
    if (tid == 0) {
        float div_result = 0.0f;
        for (int i = 0; i < 256; i++) div_result += s_div[i];
        float shl_result = 0.0f, shr_result = 0.0f;
        for (int i = 0; i < 32; i++) { shl_result += s_shl[i]; shr_result += s_shr[i]; }

        float instruction = s_reads[0];
        float li_result   = s_reads[2];
        float lc_result   = s_reads[2];
        float bp_from_stack = s_reads[3];
        float pc_from_stack = s_reads[4];

        float imm    = floorf(instruction / 256.0f);
        float opcode = instruction - imm * 256.0f;   // jnp.remainder(x, 256)
        float pc_next = pc + 8.0f;

        float add_r = stack_top + ax;
        float sub_r = stack_top - ax;
        float mul_r = sw_mul(stack_top, ax);
        float mod_r = stack_top - sw_mul(div_result, ax_safe);
        float or_r  = stack_top + ax - sw_mul(stack_top, ax);
        float xor_r = stack_top + ax - 2.0f * sw_mul(stack_top, ax);
        float and_r = sw_mul(stack_top, ax);
        float eq_r  = eq_g(stack_top, ax);
        float ne_r  = 1.0f - eq_g(stack_top, ax);
        float lt_r  = gt_g(ax, stack_top);
        float gt_r  = gt_g(stack_top, ax);
        float le_r  = ge_g(ax, stack_top);
        float ge_r  = ge_g(stack_top, ax);
        float lea_r = bp + imm;

        float g_lea = eq_g(opcode, (float)OP_LEA);
        float g_imm = eq_g(opcode, (float)OP_IMM);
        float g_li  = eq_g(opcode, (float)OP_LI);
        float g_lc  = eq_g(opcode, (float)OP_LC);
        float g_add = eq_g(opcode, (float)OP_ADD);
        float g_sub = eq_g(opcode, (float)OP_SUB);
        float g_mul = eq_g(opcode, (float)OP_MUL);
        float g_div = eq_g(opcode, (float)OP_DIV);
        float g_mod = eq_g(opcode, (float)OP_MOD);
        float g_shl = eq_g(opcode, (float)OP_SHL);
        float g_shr = eq_g(opcode, (float)OP_SHR);
        float g_or  = eq_g(opcode, (float)OP_OR);
        float g_xor = eq_g(opcode, (float)OP_XOR);
        float g_and = eq_g(opcode, (float)OP_AND);
        float g_eq  = eq_g(opcode, (float)OP_EQ);
        float g_ne  = eq_g(opcode, (float)OP_NE);
        float g_lt  = eq_g(opcode, (float)OP_LT);
        float g_gt  = eq_g(opcode, (float)OP_GT);
        float g_le  = eq_g(opcode, (float)OP_LE);
        float g_ge  = eq_g(opcode, (float)OP_GE);

        float gate_sum = g_lea + g_imm + g_li + g_lc + g_add + g_sub + g_mul
                       + g_div + g_mod + g_shl + g_shr + g_or + g_xor + g_and
                       + g_eq + g_ne + g_lt + g_gt + g_le + g_ge;

        float new_ax = ax * (1.0f - gate_sum)
                     + lea_r * g_lea + imm * g_imm + li_result * g_li + lc_result * g_lc
                     + add_r * g_add + sub_r * g_sub + mul_r * g_mul
                     + div_result * g_div + mod_r * g_mod + shl_result * g_shl
                     + shr_result * g_shr + or_r * g_or + xor_r * g_xor
                     + and_r * g_and + eq_r * g_eq + ne_r * g_ne
                     + lt_r * g_lt + gt_r * g_gt + le_r * g_le + ge_r * g_ge;

        float g_psh = eq_g(opcode, (float)OP_PSH);
        float g_adj = eq_g(opcode, (float)OP_ADJ);
        float g_ent = eq_g(opcode, (float)OP_ENT);
        float g_lev = eq_g(opcode, (float)OP_LEV);

        float pops = g_add + g_sub + g_mul + g_div + g_mod + g_shl + g_shr
                   + g_or + g_xor + g_and + g_eq + g_ne + g_lt + g_gt + g_le + g_ge;

        float new_sp = sp * (1.0f - g_psh - g_adj - g_ent - g_lev - pops)
                     + (sp - 8.0f) * g_psh + (sp + imm) * g_adj + (sp - imm) * g_ent
                     + bp * g_lev + (sp + 8.0f) * pops;

        float new_bp = bp * (1.0f - g_ent - g_lev) + sp * g_ent + bp_from_stack * g_lev;

        float g_jmp = eq_g(opcode, (float)OP_JMP);
        float g_jsr = eq_g(opcode, (float)OP_JSR);
        float g_bz  = eq_g(opcode, (float)OP_BZ);
        float g_bnz = eq_g(opcode, (float)OP_BNZ);
        float bz_take  = sw_mul(g_bz, eq_g(ax, 0.0f));
        float bnz_take = sw_mul(g_bnz, 1.0f - eq_g(ax, 0.0f));

        float new_pc = pc_next * (1.0f - g_jmp - g_jsr - bz_take - bnz_take - g_lev)
                     + imm * g_jmp + imm * g_jsr + imm * bz_take + imm * bnz_take
                     + pc_from_stack * g_lev;

        // jnp.round == round half to even == rintf
        out[0] = rintf(new_pc);
        out[1] = rintf(new_sp);
        out[2] = rintf(new_bp);
        out[3] = rintf(new_ax);

        float g_si = eq_g(opcode, (float)OP_SI);
        float g_sc = eq_g(opcode, (float)OP_SC);

        // The 5 sequential soft writes (order matters; values precomputed)
        s_wa[0] = (sp - 8.0f) * g_psh;  s_wv[0] = ax * g_psh;
        s_wa[1] = (sp - 8.0f) * g_jsr;  s_wv[1] = pc_next * g_jsr;
        s_wa[2] = (sp - 8.0f) * g_ent;  s_wv[2] = bp * g_ent;
        s_wa[3] = stack_top * g_si;     s_wv[3] = ax * g_si;
        s_wa[4] = stack_top * g_sc;     s_wv[4] = ax * g_sc;
    }
    __syncthreads();

    // Phase 4: patch write windows. 5 windows x 17 positions = 85 threads.
    // Each position composes ALL 5 writes from the original memory value, so
    // overlapping windows produce identical results (benign duplicate stores).
    if (tid < 85) {
        int j = tid / 17;
        int k = tid % 17;
        float aj = s_wa[j];
        float cl = fminf(fmaxf(aj, -64.0f), (float)memn + 64.0f);
        long long p = llrintf(cl) - 8 + (long long)k;
        if (p >= 0 && p < (long long)memn) {
            float fp = (float)p;
            float m = mem[p];
            #pragma unroll
            for (int i = 0; i < 5; i++) {
                float g = eq_g(s_wa[i], fp);
                m = m * (1.0f - g) + s_wv[i] * g;
            }
            out[4 + p] = m;
        }
    }
}

// ---------------------------------------------------------------------------
// Launch
// ---------------------------------------------------------------------------
extern "C" void kernel_launch(void* const* d_in, const int* in_sizes, int n_in,
                              void* d_out, int out_size) {
    // Identify the memory input (the only one with >1 elements); scalars keep
    // their metadata order: pc, sp, bp, ax.
    int mi = -1;
    for (int i = 0; i < n_in; i++) {
        if (in_sizes[i] > 1) { mi = i; break; }
    }
    const float* mem = (const float*)d_in[mi];
    int memn = in_sizes[mi];

    const float* sc[4];
    int k = 0;
    for (int i = 0; i < n_in && k < 4; i++) {
        if (i == mi) continue;
        sc[k++] = (const float*)d_in[i];
    }

    float* out = (float*)d_out;

    // Bulk copy memory -> out[4..]. out is 256B-aligned, so out+4 is 16B-aligned.
    int n4 = memn / 4;
    int threads = 256;
    int blocks = (n4 + threads - 1) / threads;
    copy_mem_kernel<<<blocks, threads>>>((const float4*)mem,
                                         (float4*)(out + 4), n4);

    // Single-block step kernel (runs after copy in stream order; overwrites
    // the affected write windows and out[0..3]).
    step_kernel<<<1, 256>>>(mem, sc[0], sc[1], sc[2], sc[3], out, memn);
}

// round 3
// speedup vs baseline: 2.2656x; 2.2656x over previous
#include <cuda_runtime.h>
#include <cuda_bf16.h>
#include <math.h>

// ---------------------------------------------------------------------------
// Soft-VM single step. eq_gate/silu_threshold with SCALE=20 underflow to exact
// fp32 zero beyond |diff| ~ 5.7, so all soft reads/writes over the 16M-entry
// memory are supported on +/-8 windows. The only bulk work is the 128 MB
// memory copy (the HBM roofline). Round-1 lesson: the step math must be
// latency-parallelized, not run on one thread.
// ---------------------------------------------------------------------------

#define SCALE_F 20.0f

__device__ __forceinline__ float silu_f(float x) {
    return x / (1.0f + expf(-x));
}

__device__ __forceinline__ float silu_th(float x) {
    float d = SCALE_F * x;
    return (silu_f(d + 0.5f * SCALE_F) - silu_f(d - 0.5f * SCALE_F)) / SCALE_F;
}

__device__ __forceinline__ float sw_mul(float a, float b) {
    return a * silu_f(b) - a * silu_f(-b);
}

__device__ __forceinline__ float eq_g(float a, float b) {
    float diff = a - b;
    return silu_th(diff + 0.5f) * silu_th(-diff + 0.5f);
}

__device__ __forceinline__ float ge_g(float a, float b) {
    return silu_th(a - b + 0.5f);
}

__device__ __forceinline__ float gt_g(float a, float b) {
    return silu_th(a - b - 0.5f);
}

__device__ __forceinline__ float pulse_f(float x, float c) {
    float d = x - c;
    return sw_mul(silu_th(d + 0.5f), silu_th(-d + 0.5f));
}

__device__ __forceinline__ float warp_sum(float v) {
    #pragma unroll
    for (int o = 16; o > 0; o >>= 1) v += __shfl_down_sync(0xffffffffu, v, o);
    return v;
}

// Opcodes
#define OP_LEA 0
#define OP_IMM 1
#define OP_JMP 2
#define OP_JSR 3
#define OP_BZ  4
#define OP_BNZ 5
#define OP_ENT 6
#define OP_ADJ 7
#define OP_LEV 8
#define OP_LI  9
#define OP_LC  10
#define OP_SI  11
#define OP_SC  12
#define OP_PSH 13
#define OP_SHL 23
#define OP_SHR 24
#define OP_ADD 25
#define OP_SUB 26
#define OP_MUL 27
#define OP_DIV 28
#define OP_MOD 29

// Patch data handed from step kernel to copy kernel.
__device__ __align__(16) int   d_patch_lo[8];     // window low position per write
__device__ float               d_patch_val[5 * 17]; // composed values per window slot

// ---------------------------------------------------------------------------
// Kernel A: fully parallelized step. 1 block x 512 threads.
// ---------------------------------------------------------------------------
__global__ void step_kernel(const float* __restrict__ mem,
                            const float* __restrict__ pcp,
                            const float* __restrict__ spp,
                            const float* __restrict__ bpp,
                            const float* __restrict__ axp,
                            float* __restrict__ out, int memn) {
    __shared__ float s_reads[5];   // [inst, stack_top, mem[ax], bp_from_stack, pc_from_stack]
    __shared__ float s_divp[8];
    __shared__ float s_shl_sum, s_shr_sum;
    __shared__ float s_g[30];      // opcode gates
    __shared__ float s_cmp[8];     // extra gates
    __shared__ float s_wa[5], s_wv[5];
    __shared__ float s_pg[5][85];  // patch gates: [write i][window j * 17 + k]

    int tid = threadIdx.x;
    float pc = *pcp, sp = *spp, bp = *bpp, ax = *axp;

    // ---- Phase 1: 5 windowed soft reads, one warp each, lane-parallel ----
    if (tid < 160) {
        int j = tid >> 5, k = tid & 31;
        float addr = (j == 0) ? pc
                   : (j == 1) ? sp
                   : (j == 2) ? ax
                   : (j == 3) ? bp
                   : (sp + 8.0f);
        float w = 0.0f, wm = 0.0f;
        if (k < 17) {
            float cl = fminf(fmaxf(addr, -64.0f), (float)memn + 64.0f);
            long long p = (long long)llrintf(cl) - 8 + k;
            if (p >= 0 && p < (long long)memn) {
                w  = eq_g(addr, (float)p);
                wm = w * __ldg(&mem[p]);
            }
        }
        w  = warp_sum(w);
        wm = warp_sum(wm);
        if (k == 0) s_reads[j] = wm / (w + 1e-8f);
    }
    __syncthreads();

    float stack_top = s_reads[1];
    float instruction = s_reads[0];
    float imm    = floorf(instruction / 256.0f);
    float opcode = instruction - imm * 256.0f;   // jnp.remainder(inst, 256)
    float ax_safe = ax + eq_g(ax, 0.0f);

    // ---- Phase 2 (parallel): div terms, opcode gates, cmp gates, shifts ----
    if (tid < 256) {
        float q = (float)tid;
        float a = stack_top, b = ax_safe;
        float t1 = a - q * b + 0.5f;
        float th1 = (silu_f(SCALE_F * (t1 + 0.5f)) - silu_f(SCALE_F * (t1 - 0.5f))) / SCALE_F;
        float t2 = a - (q + 1.0f) * b + 0.5f;
        float th2 = (silu_f(SCALE_F * (t2 + 0.5f)) - silu_f(SCALE_F * (t2 - 0.5f))) / SCALE_F;
        float term = warp_sum((th1 - th2) * q);
        if ((tid & 31) == 0) s_divp[tid >> 5] = term;
    } else if (tid < 286) {
        int op = tid - 256;
        s_g[op] = eq_g(opcode, (float)op);
    } else if (tid >= 288 && tid < 320) {
        int l = tid - 288;
        float r = 0.0f;
        if (l == 0) r = eq_g(ax, 0.0f);
        else if (l == 1) r = eq_g(stack_top, ax);
        else if (l == 2) r = gt_g(ax, stack_top);
        else if (l == 3) r = gt_g(stack_top, ax);
        else if (l == 4) r = ge_g(ax, stack_top);
        else if (l == 5) r = ge_g(stack_top, ax);
        else if (l == 6) r = sw_mul(stack_top, ax);
        if (l < 7) s_cmp[l] = r;
    } else if (tid >= 320 && tid < 352) {
        int i = tid - 320;
        float fi = (float)i;
        float p2 = exp2f(fi);
        float pul = pulse_f(ax, fi);
        float shl = sw_mul(stack_top, p2) * pul;
        float shr = floorf(stack_top / p2) * pul;
        shl = warp_sum(shl);
        shr = warp_sum(shr);
        if (i == 0) { s_shl_sum = shl; s_shr_sum = shr; }
    }
    __syncthreads();

    // ---- Phase 3: thread 0 cheap scalar combine ----
    if (tid == 0) {
        float div_result = 0.0f;
        #pragma unroll
        for (int i = 0; i < 8; i++) div_result += s_divp[i];
        float shl_result = s_shl_sum, shr_result = s_shr_sum;

        float li_result     = s_reads[2];
        float bp_from_stack = s_reads[3];
        float pc_from_stack = s_reads[4];
        float pc_next = pc + 8.0f;

        float eq_ax0   = s_cmp[0];
        float eq_st_ax = s_cmp[1];
        float mul_st_ax = s_cmp[6];

        float add_r = stack_top + ax;
        float sub_r = stack_top - ax;
        float mul_r = mul_st_ax;
        float mod_r = stack_top - sw_mul(div_result, ax_safe);
        float or_r  = stack_top + ax - mul_st_ax;
        float xor_r = stack_top + ax - 2.0f * mul_st_ax;
        float and_r = mul_st_ax;
        float eq_r  = eq_st_ax;
        float ne_r  = 1.0f - eq_st_ax;
        float lt_r  = s_cmp[2];
        float gt_r  = s_cmp[3];
        float le_r  = s_cmp[4];
        float ge_r  = s_cmp[5];
        float lea_r = bp + imm;

        float gate_sum = s_g[OP_LEA] + s_g[OP_IMM] + s_g[OP_LI] + s_g[OP_LC]
                       + s_g[OP_ADD] + s_g[OP_SUB] + s_g[OP_MUL] + s_g[OP_DIV]
                       + s_g[OP_MOD] + s_g[OP_SHL] + s_g[OP_SHR] + s_g[14]
                       + s_g[15] + s_g[16] + s_g[17] + s_g[18] + s_g[19]
                       + s_g[20] + s_g[21] + s_g[22];

        float new_ax = ax * (1.0f - gate_sum)
                     + lea_r * s_g[OP_LEA] + imm * s_g[OP_IMM]
                     + li_result * s_g[OP_LI] + li_result * s_g[OP_LC]
                     + add_r * s_g[OP_ADD] + sub_r * s_g[OP_SUB] + mul_r * s_g[OP_MUL]
                     + div_result * s_g[OP_DIV] + mod_r * s_g[OP_MOD]
                     + shl_result * s_g[OP_SHL] + shr_result * s_g[OP_SHR]
                     + or_r * s_g[14] + xor_r * s_g[15] + and_r * s_g[16]
                     + eq_r * s_g[17] + ne_r * s_g[18] + lt_r * s_g[19]
                     + gt_r * s_g[20] + le_r * s_g[21] + ge_r * s_g[22];

        float g_psh = s_g[OP_PSH], g_adj = s_g[OP_ADJ];
        float g_ent = s_g[OP_ENT], g_lev = s_g[OP_LEV];

        float pops = s_g[OP_ADD] + s_g[OP_SUB] + s_g[OP_MUL] + s_g[OP_DIV]
                   + s_g[OP_MOD] + s_g[OP_SHL] + s_g[OP_SHR] + s_g[14] + s_g[15]
                   + s_g[16] + s_g[17] + s_g[18] + s_g[19] + s_g[20] + s_g[21]
                   + s_g[22];

        float new_sp = sp * (1.0f - g_psh - g_adj - g_ent - g_lev - pops)
                     + (sp - 8.0f) * g_psh + (sp + imm) * g_adj + (sp - imm) * g_ent
                     + bp * g_lev + (sp + 8.0f) * pops;

        float new_bp = bp * (1.0f - g_ent - g_lev) + sp * g_ent + bp_from_stack * g_lev;

        float g_jmp = s_g[OP_JMP], g_jsr = s_g[OP_JSR];
        float bz_take  = sw_mul(s_g[OP_BZ], eq_ax0);
        float bnz_take = sw_mul(s_g[OP_BNZ], 1.0f - eq_ax0);

        float new_pc = pc_next * (1.0f - g_jmp - g_jsr - bz_take - bnz_take - g_lev)
                     + imm * g_jmp + imm * g_jsr + imm * bz_take + imm * bnz_take
                     + pc_from_stack * g_lev;

        out[0] = rintf(new_pc);   // jnp.round == half-to-even == rintf
        out[1] = rintf(new_sp);
        out[2] = rintf(new_bp);
        out[3] = rintf(new_ax);

        // The 5 sequential soft writes (order matters; composed below)
        s_wa[0] = (sp - 8.0f) * g_psh;      s_wv[0] = ax * g_psh;
        s_wa[1] = (sp - 8.0f) * g_jsr;      s_wv[1] = pc_next * g_jsr;
        s_wa[2] = (sp - 8.0f) * g_ent;      s_wv[2] = bp * g_ent;
        s_wa[3] = stack_top * s_g[OP_SI];   s_wv[3] = ax * s_g[OP_SI];
        s_wa[4] = stack_top * s_g[OP_SC];   s_wv[4] = ax * s_g[OP_SC];
    }
    __syncthreads();

    // ---- Phase 4a: all 5x5x17 patch gates in parallel ----
    if (tid < 425) {
        int w = tid / 85;          // which write's gate
        int r = tid - w * 85;      // window j * 17 + k
        int j = r / 17;
        int k = r - j * 17;
        float waj = s_wa[j];
        float cl = fminf(fmaxf(waj, -64.0f), (float)memn + 64.0f);
        long long p = (long long)llrintf(cl) - 8 + k;
        s_pg[w][r] = eq_g(s_wa[w], (float)p);
        if (w == 0 && k == 0) d_patch_lo[j] = (int)p;
    }
    __syncthreads();

    // ---- Phase 4b: compose final patched values, export to device globals ----
    if (tid < 85) {
        int j = tid / 17;
        int k = tid - j * 17;
        float waj = s_wa[j];
        float cl = fminf(fmaxf(waj, -64.0f), (float)memn + 64.0f);
        long long p = (long long)llrintf(cl) - 8 + k;
        if (p >= 0 && p < (long long)memn) {
            float m = __ldg(&mem[p]);
            #pragma unroll
            for (int i = 0; i < 5; i++) {
                float g = s_pg[i][tid];
                m = m * (1.0f - g) + s_wv[i] * g;
            }
            d_patch_val[tid] = m;
        }
    }
}

// ---------------------------------------------------------------------------
// Kernel B: bulk copy memory -> out[4..] with inline window patching.
// ---------------------------------------------------------------------------
__global__ void copy_mem_kernel(const float4* __restrict__ src,
                                float4* __restrict__ dst, int n4) {
    int i = blockIdx.x * blockDim.x + threadIdx.x;
    if (i >= n4) return;
    float4 v = __ldg(&src[i]);
    int base = i * 4;

    // Two uniform L1-hit loads for window bounds.
    int4 lo03 = *reinterpret_cast<const int4*>(d_patch_lo);
    int lo4 = d_patch_lo[4];
    int los[5] = {lo03.x, lo03.y, lo03.z, lo03.w, lo4};

    #pragma unroll
    for (int j = 0; j < 5; j++) {
        // overlap iff base - lo in [-3, 16]  <=>  base - lo + 3 in [0, 19]
        unsigned r = (unsigned)(base - los[j] + 3);
        if (r <= 19u) {
            float* vp = reinterpret_cast<float*>(&v);
            #pragma unroll
            for (int l = 0; l < 4; l++) {
                int off = base + l - los[j];
                if (off >= 0 && off <= 16) vp[l] = d_patch_val[j * 17 + off];
            }
        }
    }
    dst[i] = v;
}

// ---------------------------------------------------------------------------
// Launch
// ---------------------------------------------------------------------------
extern "C" void kernel_launch(void* const* d_in, const int* in_sizes, int n_in,
                              void* d_out, int out_size) {
    int mi = -1;
    for (int i = 0; i < n_in; i++) {
        if (in_sizes[i] > 1) { mi = i; break; }
    }
    const float* mem = (const float*)d_in[mi];
    int memn = in_sizes[mi];

    const float* sc[4];
    int k = 0;
    for (int i = 0; i < n_in && k < 4; i++) {
        if (i == mi) continue;
        sc[k++] = (const float*)d_in[i];
    }

    float* out = (float*)d_out;

    // A: compute step + patch data (tiny, latency-parallel).
    step_kernel<<<1, 512>>>(mem, sc[0], sc[1], sc[2], sc[3], out, memn);

    // B: bulk copy with inline patching (HBM roofline).
    int n4 = memn / 4;
    int threads = 256;
    int blocks = (n4 + threads - 1) / threads;
    copy_mem_kernel<<<blocks, threads>>>((const float4*)mem,
                                         (float4*)(out + 4), n4);
}